// round 4
// baseline (speedup 1.0000x reference)
#include <cuda_runtime.h>
#include <cuda_bf16.h>
#include <cstddef>
#include <cstdint>

#define N_  16
#define K_  256
#define T_  1000
#define M_  384
#define P_  2
#define C8  8
#define TT  8      // t-rows per score block

typedef unsigned long long u64;

// ---------------- scratch (device globals; no allocations) ----------------
__device__ float g_SE[N_ * K_ * 2];    // S, E per (n,k)
__device__ float g_g [N_ * K_ * 16];   // folded layer-1 bias per (n,k)
__device__ float g_ga[N_ * K_ * 2];    // folded aux layer-1 bias per (n,k)
__device__ float g_W [N_ * T_ * K_];   // softmax weights
__device__ float g_wc[N_ * T_ * 2];    // sum_k W*C  (before proj)

// ---------------- packed fp32x2 helpers ---------------
__device__ __forceinline__ u64 pk2(float lo, float hi) {
    u64 d; asm("mov.b64 %0, {%1, %2};" : "=l"(d) : "f"(lo), "f"(hi)); return d;
}
__device__ __forceinline__ u64 pkd(float x) {
    u64 d; asm("mov.b64 %0, {%1, %1};" : "=l"(d) : "f"(x)); return d;
}
__device__ __forceinline__ void upk(u64 v, float& lo, float& hi) {
    asm("mov.b64 {%0, %1}, %2;" : "=f"(lo), "=f"(hi) : "l"(v));
}
__device__ __forceinline__ u64 ffma2(u64 a, u64 b, u64 c) {
    u64 d; asm("fma.rn.f32x2 %0, %1, %2, %3;" : "=l"(d) : "l"(a), "l"(b), "l"(c));
    return d;
}

// silu via single-MUFU tanh.approx
__device__ __forceinline__ float siluf(float x) {
    float th;
    const float hx = 0.5f * x;
    asm("tanh.approx.f32 %0, %1;" : "=f"(th) : "f"(hx));
    return fmaf(hx, th, hx);
}

__device__ __forceinline__ uint32_t tf32cvt(float x) {
    uint32_t r; asm("cvt.rna.tf32.f32 %0, %1;" : "=r"(r) : "f"(x)); return r;
}

__device__ __forceinline__ void mma_tf32(float d[4], const uint32_t a[4],
                                         const uint32_t b[2]) {
    asm("mma.sync.aligned.m16n8k8.row.col.f32.tf32.tf32.f32 "
        "{%0,%1,%2,%3}, {%4,%5,%6,%7}, {%8,%9}, {%0,%1,%2,%3};"
        : "+f"(d[0]), "+f"(d[1]), "+f"(d[2]), "+f"(d[3])
        : "r"(a[0]), "r"(a[1]), "r"(a[2]), "r"(a[3]), "r"(b[0]), "r"(b[1]));
}

// ---------------------------------------------------------------------------
// Kernel 0: durations + scan -> S,E.  Grid N_, block K_.
// ---------------------------------------------------------------------------
__global__ void scan_kernel(const float* __restrict__ dur_out)
{
    __shared__ float wsum[8];
    const int n = blockIdx.x;
    const int k = threadIdx.x;
    const int lane = k & 31, warp = k >> 5;

    const float d = fmaxf(__expf(dur_out[n * K_ + k]) - 1.0f, 0.0f);
    float x = d;
#pragma unroll
    for (int off = 1; off < 32; off <<= 1) {
        float y = __shfl_up_sync(0xFFFFFFFFu, x, off);
        if (lane >= off) x += y;
    }
    if (lane == 31) wsum[warp] = x;
    __syncthreads();
    float off = 0.0f;
#pragma unroll
    for (int w = 0; w < 8; w++) off += (w < warp) ? wsum[w] : 0.0f;
    const float Ev = x + off;
    const float Sv = Ev - d;
    g_SE[(n * K_ + k) * 2 + 0] = Sv;
    g_SE[(n * K_ + k) * 2 + 1] = Ev;
}

// ---------------------------------------------------------------------------
// Kernel 1: Conv1D(3,same)+BN+silu and fold into g/ga. One warp per (n,k).
// ---------------------------------------------------------------------------
__global__ __launch_bounds__(256) void conv_fold_kernel(
    const float* __restrict__ V,
    const float* __restrict__ conv_w,
    const float* __restrict__ conv_b,
    const float* __restrict__ bn_gamma, const float* __restrict__ bn_beta,
    const float* __restrict__ bn_mean,  const float* __restrict__ bn_var,
    const float* __restrict__ w1,
    const float* __restrict__ b1,
    const float* __restrict__ aw1,
    const float* __restrict__ ab1)
{
    const int tid  = threadIdx.x;
    const int lane = tid & 31;
    const int widx = blockIdx.x * 8 + (tid >> 5);
    const int n = widx >> 8;
    const int k = widx & 255;

    u64 acc2[4] = {0ull, 0ull, 0ull, 0ull};

#pragma unroll
    for (int tap = 0; tap < 3; tap++) {
        const int kk = k - 1 + tap;
        if (kk < 0 || kk >= K_) continue;
        const float* vrow = V + ((size_t)n * K_ + kk) * M_;
#pragma unroll
        for (int i = 0; i < 3; i++) {
            const int c0 = i * 128 + lane * 4;
            const float4 v = *reinterpret_cast<const float4*>(vrow + c0);
            const float vv[4] = { v.x, v.y, v.z, v.w };
#pragma unroll
            for (int cc = 0; cc < 4; cc++) {
                const u64 vd = pkd(vv[cc]);
                const float4* wp = reinterpret_cast<const float4*>(
                    conv_w + ((size_t)tap * M_ + c0 + cc) * 8);
                const float4 wa = wp[0], wb = wp[1];
                acc2[0] = ffma2(vd, pk2(wa.x, wa.y), acc2[0]);
                acc2[1] = ffma2(vd, pk2(wa.z, wa.w), acc2[1]);
                acc2[2] = ffma2(vd, pk2(wb.x, wb.y), acc2[2]);
                acc2[3] = ffma2(vd, pk2(wb.z, wb.w), acc2[3]);
            }
        }
    }

    float acc[8];
#pragma unroll
    for (int j = 0; j < 4; j++) upk(acc2[j], acc[2 * j], acc[2 * j + 1]);
#pragma unroll
    for (int s = 16; s > 0; s >>= 1)
#pragma unroll
        for (int o = 0; o < 8; o++)
            acc[o] += __shfl_xor_sync(0xFFFFFFFFu, acc[o], s);

    float cv[8];
#pragma unroll
    for (int o = 0; o < 8; o++) {
        float y = (acc[o] + conv_b[o] - bn_mean[o]) * rsqrtf(bn_var[o] + 1e-3f)
                  * bn_gamma[o] + bn_beta[o];
        cv[o] = siluf(y);
    }

    const float Sv = g_SE[(n * K_ + k) * 2 + 0];
    const float Ev = g_SE[(n * K_ + k) * 2 + 1];

    if (lane < 16) {
        const int j = lane;
        float gj = b1[j] - Sv * w1[j] + Ev * w1[16 + j];
#pragma unroll
        for (int c = 0; c < 8; c++) gj = fmaf(cv[c], w1[(2 + c) * 16 + j], gj);
        g_g[((size_t)n * K_ + k) * 16 + j] = gj;
    } else if (lane < 18) {
        const int p = lane - 16;
        float gp = ab1[p] - Sv * aw1[p] + Ev * aw1[2 + p];
#pragma unroll
        for (int c = 0; c < 8; c++) gp = fmaf(cv[c], aw1[(2 + c) * 2 + p], gp);
        g_ga[((size_t)n * K_ + k) * 2 + p] = gp;
    }
}

// ---------------------------------------------------------------------------
// Kernel 2: score MLP + softmax + aux per (n, t-tile of TT). Block = K_ threads.
// ---------------------------------------------------------------------------
__global__ __launch_bounds__(256) void score_kernel(
    const float* __restrict__ w1,
    const float* __restrict__ w2,
    const float* __restrict__ b2,
    const float* __restrict__ w3,
    const float* __restrict__ b3,
    const float* __restrict__ aw1,
    const float* __restrict__ aw2,
    const float* __restrict__ ab2)
{
    __shared__ float2 s_w2p[16][8];
    __shared__ float s_d1[16], s_w3[16], s_b2[16];
    __shared__ float s_da[2], s_aw2[4], s_ab2[2], s_b3v;
    __shared__ float smax[2][8];
    __shared__ float spart[2][8][4];

    const int k    = threadIdx.x;
    const int lane = k & 31, warp = k >> 5;
    const int n    = blockIdx.y;
    const int tb   = blockIdx.x * TT;

    if (k < 128) {
        const int i = k & 15, j2 = k >> 4;
        s_w2p[i][j2] = make_float2(w2[(2 * j2) * 16 + i], w2[(2 * j2 + 1) * 16 + i]);
    }
    if (k < 16) { s_d1[k] = w1[k] - w1[16 + k]; s_w3[k] = w3[k]; s_b2[k] = b2[k]; }
    if (k < 2)  { s_da[k] = aw1[k] - aw1[2 + k]; s_ab2[k] = ab2[k]; }
    if (k < 4)  { s_aw2[k] = aw2[k]; }
    if (k == 0) { s_b3v = b3[0]; }
    __syncthreads();

    float g[16];
    {
        const float4* gp = reinterpret_cast<const float4*>(g_g + ((size_t)n * K_ + k) * 16);
#pragma unroll
        for (int q = 0; q < 4; q++) {
            float4 v = gp[q];
            g[4 * q] = v.x; g[4 * q + 1] = v.y; g[4 * q + 2] = v.z; g[4 * q + 3] = v.w;
        }
    }
    const float ga0 = g_ga[((size_t)n * K_ + k) * 2 + 0];
    const float ga1 = g_ga[((size_t)n * K_ + k) * 2 + 1];

    for (int tt = 0; tt < TT; tt++) {
        const int p = tt & 1;
        const float t = (float)(tb + tt + 1);

        u64 h2[8];
#pragma unroll
        for (int j2 = 0; j2 < 8; j2++) {
            float a = siluf(fmaf(t, s_d1[2 * j2],     g[2 * j2]));
            float b = siluf(fmaf(t, s_d1[2 * j2 + 1], g[2 * j2 + 1]));
            h2[j2] = pk2(a, b);
        }
        float score = s_b3v;
#pragma unroll
        for (int i = 0; i < 16; i++) {
            u64 acc = pk2(s_b2[i], 0.0f);
            const u64* wrow = reinterpret_cast<const u64*>(&s_w2p[i][0]);
#pragma unroll
            for (int j2 = 0; j2 < 8; j2++) acc = ffma2(h2[j2], wrow[j2], acc);
            float lo, hi; upk(acc, lo, hi);
            score = fmaf(siluf(lo + hi), s_w3[i], score);
        }

        const float a0 = siluf(fmaf(t, s_da[0], ga0));
        const float a1 = siluf(fmaf(t, s_da[1], ga1));
        const float c20 = siluf(s_ab2[0] + a0 * s_aw2[0] + a1 * s_aw2[2]);
        const float c21 = siluf(s_ab2[1] + a0 * s_aw2[1] + a1 * s_aw2[3]);

        float m = score;
#pragma unroll
        for (int s = 16; s > 0; s >>= 1) m = fmaxf(m, __shfl_xor_sync(0xFFFFFFFFu, m, s));
        if (lane == 0) smax[p][warp] = m;
        __syncthreads();
        float mx = smax[p][0];
#pragma unroll
        for (int w = 1; w < 8; w++) mx = fmaxf(mx, smax[p][w]);

        const float e = __expf(score - mx);
        float s0 = e, s1 = e * c20, s2 = e * c21;
#pragma unroll
        for (int s = 16; s > 0; s >>= 1) {
            s0 += __shfl_xor_sync(0xFFFFFFFFu, s0, s);
            s1 += __shfl_xor_sync(0xFFFFFFFFu, s1, s);
            s2 += __shfl_xor_sync(0xFFFFFFFFu, s2, s);
        }
        if (lane == 0) {
            spart[p][warp][0] = s0; spart[p][warp][1] = s1; spart[p][warp][2] = s2;
        }
        __syncthreads();
        float t0s = 0.0f, t1s = 0.0f, t2s = 0.0f;
#pragma unroll
        for (int w = 0; w < 8; w++) {
            t0s += spart[p][w][0]; t1s += spart[p][w][1]; t2s += spart[p][w][2];
        }
        const float inv = __fdividef(1.0f, t0s);

        g_W[((size_t)n * T_ + (tb + tt)) * K_ + k] = e * inv;
        if (k == 0) {
            g_wc[((size_t)n * T_ + (tb + tt)) * 2 + 0] = t1s * inv;
            g_wc[((size_t)n * T_ + (tb + tt)) * 2 + 1] = t2s * inv;
        }
    }
}

// ---------------------------------------------------------------------------
// Kernel 3: O = W @ V + wc @ proj_w via 3xTF32 mma.sync (m16n8k8).
// CTA tile 128x128, 8 warps (2m x 4n), warp tile 64x32, K-chunk = 16.
// Loader pre-permutes (hi,lo) tf32 pairs into exact fragment layout so the
// compute loop uses only conflict-free LDS.128.
// ---------------------------------------------------------------------------
__global__ __launch_bounds__(256) void out_gemm_kernel(
    const float* __restrict__ V,       // [N,K,M]
    const float* __restrict__ proj_w,  // [2,M]
    float* __restrict__ O)             // [N,T,M]
{
    // A frags: [kstep(2)][mtile(8)][half(2)][lane(32)] x 16B  -> 16KB
    // B frags: [kstep(2)][ntile(16)][lane(32)] x 16B          -> 16KB
    __shared__ __align__(16) uint2 sA[2048];
    __shared__ __align__(16) uint2 sB[2048];

    const int n  = blockIdx.z;
    const int t0 = blockIdx.y * 128;
    const int m0 = blockIdx.x * 128;

    const int tid  = threadIdx.x;
    const int lane = tid & 31;
    const int wid  = tid >> 5;
    const int wm   = wid >> 2;      // 0..1
    const int wn   = wid & 3;       // 0..3

    const float* A = g_W + (size_t)n * T_ * K_;   // [T,K]
    const float* B = V   + (size_t)n * K_ * M_;   // [K,M]

    // ---- loader indices ----
    const int a_t   = tid >> 1;                    // 0..127  (row in tile)
    const int a_ks  = tid & 1;                     // kstep within chunk
    const int a_mt  = a_t >> 4;
    const int a_r   = a_t & 15;
    const int a_slot= a_r >> 3;
    const int tg    = t0 + a_t;
    const float* Abase = A + (size_t)((tg < T_) ? tg : (T_ - 1)) * K_ + a_ks * 8;

    const int b_kk  = tid >> 4;                    // 0..15 (k row in chunk)
    const int b_ks  = b_kk >> 3;
    const int b_kr  = b_kk & 7;
    const int b_nt  = tid & 15;                    // ntile
    const int b_reg = b_kr >> 2;
    const float* Bbase = B + (size_t)b_kk * M_ + m0 + b_nt * 8;

    float4 av0, av1, bv0, bv1;

    // prefetch chunk 0
    av0 = *reinterpret_cast<const float4*>(Abase);
    av1 = *reinterpret_cast<const float4*>(Abase + 4);
    bv0 = *reinterpret_cast<const float4*>(Bbase);
    bv1 = *reinterpret_cast<const float4*>(Bbase + 4);

    float d[4][4][4];
#pragma unroll
    for (int i = 0; i < 4; i++)
#pragma unroll
        for (int j = 0; j < 4; j++)
#pragma unroll
            for (int q = 0; q < 4; q++) d[i][j][q] = 0.0f;

    const int NCHUNK = K_ / 16;     // 16

    for (int chunk = 0; chunk < NCHUNK; chunk++) {
        // ---- store current regs into fragment-layout smem ----
        {
            const float ae[8] = { av0.x, av0.y, av0.z, av0.w,
                                  av1.x, av1.y, av1.z, av1.w };
#pragma unroll
            for (int e = 0; e < 8; e++) {
                const uint32_t hi = tf32cvt(ae[e]);
                const uint32_t lo = tf32cvt(ae[e] - __uint_as_float(hi));
                const int half = e >> 2;
                const int alane = ((a_r & 7) << 2) | (e & 3);
                const int addr = ((((a_ks * 8 + a_mt) * 2 + half) * 32 + alane) << 1) + a_slot;
                sA[addr] = make_uint2(hi, lo);
            }
            const float be[8] = { bv0.x, bv0.y, bv0.z, bv0.w,
                                  bv1.x, bv1.y, bv1.z, bv1.w };
#pragma unroll
            for (int e = 0; e < 8; e++) {
                const uint32_t hi = tf32cvt(be[e]);
                const uint32_t lo = tf32cvt(be[e] - __uint_as_float(hi));
                const int blane = (e << 2) | (b_kr & 3);
                const int addr = (((b_ks * 16 + b_nt) * 32 + blane) << 1) + b_reg;
                sB[addr] = make_uint2(hi, lo);
            }
        }
        __syncthreads();

        // ---- prefetch next chunk ----
        if (chunk + 1 < NCHUNK) {
            const float* Ap = Abase + (chunk + 1) * 16;
            const float* Bp = Bbase + (size_t)(chunk + 1) * 16 * M_;
            av0 = *reinterpret_cast<const float4*>(Ap);
            av1 = *reinterpret_cast<const float4*>(Ap + 4);
            bv0 = *reinterpret_cast<const float4*>(Bp);
            bv1 = *reinterpret_cast<const float4*>(Bp + 4);
        }

        // ---- compute: 2 ksteps x (4 mtiles x 4 ntiles) x 3 mma ----
#pragma unroll
        for (int ks = 0; ks < 2; ks++) {
            uint32_t bh[4][2], bl[4][2];
#pragma unroll
            for (int j = 0; j < 4; j++) {
                const int nt = wn * 4 + j;
                const uint4 q = *reinterpret_cast<const uint4*>(
                    &sA[0] + 0);  // placeholder avoided below
                (void)q;
                const uint4 r = reinterpret_cast<const uint4*>(sB)[(ks * 16 + nt) * 32 + lane];
                bh[j][0] = r.x; bl[j][0] = r.y;
                bh[j][1] = r.z; bl[j][1] = r.w;
            }
#pragma unroll
            for (int i = 0; i < 4; i++) {
                const int mt = wm * 4 + i;
                const uint4 q0 = reinterpret_cast<const uint4*>(sA)[((ks * 8 + mt) * 2 + 0) * 32 + lane];
                const uint4 q1 = reinterpret_cast<const uint4*>(sA)[((ks * 8 + mt) * 2 + 1) * 32 + lane];
                uint32_t ah[4] = { q0.x, q0.z, q1.x, q1.z };
                uint32_t al[4] = { q0.y, q0.w, q1.y, q1.w };
#pragma unroll
                for (int j = 0; j < 4; j++) {
                    mma_tf32(d[i][j], ah, bh[j]);
                    mma_tf32(d[i][j], ah, bl[j]);
                    mma_tf32(d[i][j], al, bh[j]);
                }
            }
        }
        __syncthreads();
    }

    // ---- epilogue: += wc @ proj_w, store float2 per (row, 2 cols) ----
    float pj0[4][2], pj1[4][2];
#pragma unroll
    for (int j = 0; j < 4; j++) {
        const int m = m0 + wn * 32 + j * 8 + (lane & 3) * 2;
        pj0[j][0] = proj_w[m];          pj0[j][1] = proj_w[m + 1];
        pj1[j][0] = proj_w[M_ + m];     pj1[j][1] = proj_w[M_ + m + 1];
    }

#pragma unroll
    for (int i = 0; i < 4; i++) {
        const int tr0 = t0 + wm * 64 + i * 16 + (lane >> 2);
#pragma unroll
        for (int half = 0; half < 2; half++) {
            const int tr = tr0 + half * 8;
            if (tr >= T_) continue;
            const float wc0 = g_wc[((size_t)n * T_ + tr) * 2 + 0];
            const float wc1 = g_wc[((size_t)n * T_ + tr) * 2 + 1];
#pragma unroll
            for (int j = 0; j < 4; j++) {
                const int m = m0 + wn * 32 + j * 8 + (lane & 3) * 2;
                float2 out;
                out.x = d[i][j][half * 2 + 0] + wc0 * pj0[j][0] + wc1 * pj1[j][0];
                out.y = d[i][j][half * 2 + 1] + wc0 * pj0[j][1] + wc1 * pj1[j][1];
                *reinterpret_cast<float2*>(&O[((size_t)n * T_ + tr) * M_ + m]) = out;
            }
        }
    }
}

// ---------------------------------------------------------------------------
extern "C" void kernel_launch(void* const* d_in, const int* in_sizes, int n_in,
                              void* d_out, int out_size)
{
    const float* V        = (const float*)d_in[0];
    const float* dur      = (const float*)d_in[1];
    const float* conv_w   = (const float*)d_in[2];
    const float* conv_b   = (const float*)d_in[3];
    const float* bn_gamma = (const float*)d_in[4];
    const float* bn_beta  = (const float*)d_in[5];
    const float* bn_mean  = (const float*)d_in[6];
    const float* bn_var   = (const float*)d_in[7];
    const float* w1       = (const float*)d_in[8];
    const float* b1       = (const float*)d_in[9];
    const float* w2       = (const float*)d_in[10];
    const float* b2       = (const float*)d_in[11];
    const float* w3       = (const float*)d_in[12];
    const float* b3       = (const float*)d_in[13];
    const float* aw1      = (const float*)d_in[14];
    const float* ab1      = (const float*)d_in[15];
    const float* aw2      = (const float*)d_in[16];
    const float* ab2      = (const float*)d_in[17];
    const float* proj_w   = (const float*)d_in[18];
    float* O = (float*)d_out;

    scan_kernel<<<N_, K_>>>(dur);
    conv_fold_kernel<<<(N_ * K_) / 8, 256>>>(V, conv_w, conv_b, bn_gamma, bn_beta,
                                             bn_mean, bn_var, w1, b1, aw1, ab1);
    score_kernel<<<dim3(T_ / TT, N_), K_>>>(w1, w2, b2, w3, b3, aw1, aw2, ab2);
    out_gemm_kernel<<<dim3(M_ / 128, (T_ + 127) / 128, N_), 256>>>(V, proj_w, O);
}